// round 1
// baseline (speedup 1.0000x reference)
#include <cuda_runtime.h>

// ---------------------------------------------------------------------------
// GCN: 3 layers. out = Ahat @ (X @ W) + b, relu on layers 1,2.
// Ahat = D^-1/2 (A + I) D^-1/2 with in-degree over dst (weighted) + self loops.
//
// Strategy:
//   1. Build dst-sorted CSR (histogram -> scan -> atomic scatter). Once per call.
//   2. Per layer: dense fp32 GEMM (register-tiled), then warp-per-node
//      segmented reduction (no atomics, float4 gathers from L2-resident H).
// ---------------------------------------------------------------------------

#define N_NODES 50000
#define N_EDGES 800000

// ----- device scratch (static globals: allocation-free) -----
__device__ float g_deg[N_NODES];
__device__ float g_dis[N_NODES];
__device__ int   g_counts[N_NODES];
__device__ int   g_offsets[N_NODES];     // exclusive starts; mutated by scatter
__device__ int   g_blocksums[64];
__device__ int   g_src_sorted[N_EDGES];
__device__ float g_norm_sorted[N_EDGES];
__device__ float g_bufA[(size_t)N_NODES * 128];
__device__ float g_bufB[(size_t)N_NODES * 128];

// ---------------------------------------------------------------------------
// Setup kernels
// ---------------------------------------------------------------------------
__global__ void k_init(int n) {
    int i = blockIdx.x * blockDim.x + threadIdx.x;
    if (i < n) {
        g_deg[i]    = 1.0f;   // self-loop weight
        g_counts[i] = 0;
    }
}

__global__ void k_deg_count(const int* __restrict__ ei,
                            const float* __restrict__ ew, int E) {
    int e = blockIdx.x * blockDim.x + threadIdx.x;
    if (e < E) {
        int d = ei[E + e];                 // dst
        atomicAdd(&g_deg[d], ew[e]);
        atomicAdd(&g_counts[d], 1);
    }
}

__global__ void k_dis(int n) {
    int i = blockIdx.x * blockDim.x + threadIdx.x;
    if (i < n) {
        float d = g_deg[i];
        g_dis[i] = (d > 0.0f) ? rsqrtf(d) : 0.0f;
    }
}

// Block-level exclusive scan of g_counts -> g_offsets, block totals -> g_blocksums
__global__ void k_scan1(int n) {
    __shared__ int sh[1024];
    int tid = threadIdx.x;
    int gid = blockIdx.x * 1024 + tid;
    int v = (gid < n) ? g_counts[gid] : 0;
    sh[tid] = v;
    __syncthreads();
    for (int off = 1; off < 1024; off <<= 1) {
        int t = (tid >= off) ? sh[tid - off] : 0;
        __syncthreads();
        sh[tid] += t;
        __syncthreads();
    }
    int incl = sh[tid];
    if (gid < n) g_offsets[gid] = incl - v;       // exclusive
    if (tid == 1023) g_blocksums[blockIdx.x] = incl;
}

__global__ void k_scan2(int nb) {
    __shared__ int sh[64];
    int tid = threadIdx.x;               // 64 threads
    int v = (tid < nb) ? g_blocksums[tid] : 0;
    sh[tid] = v;
    __syncthreads();
    for (int off = 1; off < 64; off <<= 1) {
        int t = (tid >= off) ? sh[tid - off] : 0;
        __syncthreads();
        sh[tid] += t;
        __syncthreads();
    }
    if (tid < nb) g_blocksums[tid] = sh[tid] - v;  // exclusive
}

__global__ void k_scan3(int n) {
    int gid = blockIdx.x * 1024 + threadIdx.x;
    if (gid < n) g_offsets[gid] += g_blocksums[blockIdx.x];
}

// Scatter edges into dst-sorted order. Mutates g_offsets: after this kernel
// g_offsets[i] == end of segment i, and start of segment i == (i?g_offsets[i-1]:0).
__global__ void k_scatter(const int* __restrict__ ei,
                          const float* __restrict__ ew, int E) {
    int e = blockIdx.x * blockDim.x + threadIdx.x;
    if (e < E) {
        int s = ei[e];
        int d = ei[E + e];
        int pos = atomicAdd(&g_offsets[d], 1);
        g_src_sorted[pos]  = s;
        g_norm_sorted[pos] = g_dis[s] * ew[e] * g_dis[d];
    }
}

// ---------------------------------------------------------------------------
// Dense GEMM: Y[n, FOUT] = X[n, K] @ W[K, FOUT]
// Block: 256 threads, tile 64 rows x FOUT cols, each thread 8 rows x FOUT/32 cols.
// ---------------------------------------------------------------------------
template <int K, int FOUT>
__launch_bounds__(256, 2)
__global__ void k_gemm(const float* __restrict__ X, const float* __restrict__ W,
                       float* __restrict__ Y, int nrows) {
    constexpr int KC  = 32;
    constexpr int CPT = FOUT / 32;       // cols per thread (4 or 2)
    __shared__ float Xs[64][KC + 1];
    __shared__ float Ws[KC][FOUT];

    int tid  = threadIdx.x;
    int tx   = tid & 31;
    int ty   = tid >> 5;                 // 0..7
    int row0 = blockIdx.x * 64;

    float acc[8][CPT];
#pragma unroll
    for (int r = 0; r < 8; r++)
#pragma unroll
        for (int j = 0; j < CPT; j++) acc[r][j] = 0.0f;

    for (int k0 = 0; k0 < K; k0 += KC) {
        // stage X tile: 64*32 elems, 8 per thread
#pragma unroll
        for (int i = 0; i < 8; i++) {
            int idx = tid + i * 256;
            int r = idx >> 5, c = idx & 31;
            int gr = row0 + r;
            Xs[r][c] = (gr < nrows) ? X[(size_t)gr * K + k0 + c] : 0.0f;
        }
        // stage W tile: KC*FOUT elems
#pragma unroll
        for (int i = 0; i < (KC * FOUT) / 256; i++) {
            int idx = tid + i * 256;
            int kk = idx / FOUT, c = idx % FOUT;
            Ws[kk][c] = W[(size_t)(k0 + kk) * FOUT + c];
        }
        __syncthreads();

#pragma unroll
        for (int kk = 0; kk < KC; kk++) {
            float a[8];
#pragma unroll
            for (int r = 0; r < 8; r++) a[r] = Xs[ty * 8 + r][kk];
            float wv[CPT];
#pragma unroll
            for (int j = 0; j < CPT; j++) wv[j] = Ws[kk][tx + 32 * j];
#pragma unroll
            for (int r = 0; r < 8; r++)
#pragma unroll
                for (int j = 0; j < CPT; j++) acc[r][j] += a[r] * wv[j];
        }
        __syncthreads();
    }

#pragma unroll
    for (int r = 0; r < 8; r++) {
        int gr = row0 + ty * 8 + r;
        if (gr < nrows) {
#pragma unroll
            for (int j = 0; j < CPT; j++)
                Y[(size_t)gr * FOUT + tx + 32 * j] = acc[r][j];
        }
    }
}

// ---------------------------------------------------------------------------
// Aggregation: one warp per node. out[i] = sum_e norm_e * H[src_e] +
//              dis[i]^2 * H[i] + b   (optional relu)
// ---------------------------------------------------------------------------
template <int F, bool RELU>
__launch_bounds__(256)
__global__ void k_agg(const float* __restrict__ H, const float* __restrict__ bias,
                      float* __restrict__ out, int n) {
    int warp = (blockIdx.x * blockDim.x + threadIdx.x) >> 5;
    int lane = threadIdx.x & 31;
    if (warp >= n) return;

    constexpr int VEC = F / 32;          // 4 (F=128) or 2 (F=64)
    int s = (warp == 0) ? 0 : g_offsets[warp - 1];
    int e = g_offsets[warp];
    int col = lane * VEC;

    if constexpr (VEC == 4) {
        float4 acc = make_float4(0.f, 0.f, 0.f, 0.f);
        for (int j = s; j < e; j++) {
            int   sn = g_src_sorted[j];
            float nw = g_norm_sorted[j];
            float4 v = *(const float4*)(H + (size_t)sn * F + col);
            acc.x += nw * v.x; acc.y += nw * v.y;
            acc.z += nw * v.z; acc.w += nw * v.w;
        }
        float dv = g_dis[warp];
        float sw = dv * dv;
        float4 v = *(const float4*)(H + (size_t)warp * F + col);
        acc.x += sw * v.x; acc.y += sw * v.y;
        acc.z += sw * v.z; acc.w += sw * v.w;
        float4 b = *(const float4*)(bias + col);
        acc.x += b.x; acc.y += b.y; acc.z += b.z; acc.w += b.w;
        if (RELU) {
            acc.x = fmaxf(acc.x, 0.f); acc.y = fmaxf(acc.y, 0.f);
            acc.z = fmaxf(acc.z, 0.f); acc.w = fmaxf(acc.w, 0.f);
        }
        *(float4*)(out + (size_t)warp * F + col) = acc;
    } else {
        float2 acc = make_float2(0.f, 0.f);
        for (int j = s; j < e; j++) {
            int   sn = g_src_sorted[j];
            float nw = g_norm_sorted[j];
            float2 v = *(const float2*)(H + (size_t)sn * F + col);
            acc.x += nw * v.x; acc.y += nw * v.y;
        }
        float dv = g_dis[warp];
        float sw = dv * dv;
        float2 v = *(const float2*)(H + (size_t)warp * F + col);
        acc.x += sw * v.x; acc.y += sw * v.y;
        float2 b = *(const float2*)(bias + col);
        acc.x += b.x; acc.y += b.y;
        if (RELU) { acc.x = fmaxf(acc.x, 0.f); acc.y = fmaxf(acc.y, 0.f); }
        *(float2*)(out + (size_t)warp * F + col) = acc;
    }
}

// ---------------------------------------------------------------------------
// Launch
// ---------------------------------------------------------------------------
extern "C" void kernel_launch(void* const* d_in, const int* in_sizes, int n_in,
                              void* d_out, int out_size) {
    const float* x  = (const float*)d_in[0];
    const int*   ei = (const int*)  d_in[1];
    const float* ew = (const float*)d_in[2];
    const float* W1 = (const float*)d_in[3];
    const float* b1 = (const float*)d_in[4];
    const float* W2 = (const float*)d_in[5];
    const float* b2 = (const float*)d_in[6];
    const float* W3 = (const float*)d_in[7];
    const float* b3 = (const float*)d_in[8];
    float* out = (float*)d_out;

    const int n = N_NODES;
    const int E = N_EDGES;

    // device-global pointers (same module; __device__ symbols addressable directly
    // from device code; for host launches we just pass nothing — kernels use the
    // globals directly).
    float* bufA;  float* bufB;
    cudaGetSymbolAddress((void**)&bufA, g_bufA);
    cudaGetSymbolAddress((void**)&bufB, g_bufB);

    const int TPB = 256;
    int nbN = (n + TPB - 1) / TPB;
    int nbE = (E + TPB - 1) / TPB;
    int nbScan = (n + 1023) / 1024;     // 49

    // ---- build normalization + CSR ----
    k_init<<<nbN, TPB>>>(n);
    k_deg_count<<<nbE, TPB>>>(ei, ew, E);
    k_dis<<<nbN, TPB>>>(n);
    k_scan1<<<nbScan, 1024>>>(n);
    k_scan2<<<1, 64>>>(nbScan);
    k_scan3<<<nbScan, 1024>>>(n);
    k_scatter<<<nbE, TPB>>>(ei, ew, E);

    int gemmBlocks = (n + 63) / 64;
    int aggBlocks  = (n * 32 + TPB - 1) / TPB;

    // ---- layer 1: 256 -> 128, relu ----
    k_gemm<256, 128><<<gemmBlocks, 256>>>(x, W1, bufA, n);
    k_agg<128, true><<<aggBlocks, TPB>>>(bufA, b1, bufB, n);

    // ---- layer 2: 128 -> 128, relu ----
    k_gemm<128, 128><<<gemmBlocks, 256>>>(bufB, W2, bufA, n);
    k_agg<128, true><<<aggBlocks, TPB>>>(bufA, b2, bufB, n);

    // ---- layer 3: 128 -> 64, no relu ----
    k_gemm<128, 64><<<gemmBlocks, 256>>>(bufB, W3, bufA, n);
    k_agg<64, false><<<aggBlocks, TPB>>>(bufA, b3, out, n);
}

// round 2
// speedup vs baseline: 1.4846x; 1.4846x over previous
#include <cuda_runtime.h>
#include <cuda_bf16.h>
#include <cstdint>

// ---------------------------------------------------------------------------
// GCN: 3 layers. out = Ahat @ (X @ W) + b, relu on layers 1,2.
//
// R2: GEMMs moved to bf16 tensor cores (mma.sync m16n8k16) with 2-term
// bf16 split (hi+lo, 3 MMAs) for fp32-grade accuracy. Split happens during
// smem staging from the fp32 operands, so agg/CSR path is unchanged.
// ---------------------------------------------------------------------------

#define N_NODES 50000
#define N_EDGES 800000

// ----- device scratch (static globals: allocation-free) -----
__device__ float g_deg[N_NODES];
__device__ float g_dis[N_NODES];
__device__ int   g_counts[N_NODES];
__device__ int   g_offsets[N_NODES];     // exclusive starts; mutated by scatter
__device__ int   g_blocksums[64];
__device__ int   g_src_sorted[N_EDGES];
__device__ float g_norm_sorted[N_EDGES];
__device__ float g_bufA[(size_t)N_NODES * 128];
__device__ float g_bufB[(size_t)N_NODES * 128];

// ---------------------------------------------------------------------------
// Setup kernels (unchanged)
// ---------------------------------------------------------------------------
__global__ void k_init(int n) {
    int i = blockIdx.x * blockDim.x + threadIdx.x;
    if (i < n) {
        g_deg[i]    = 1.0f;   // self-loop weight
        g_counts[i] = 0;
    }
}

__global__ void k_deg_count(const int* __restrict__ ei,
                            const float* __restrict__ ew, int E) {
    int e = blockIdx.x * blockDim.x + threadIdx.x;
    if (e < E) {
        int d = ei[E + e];                 // dst
        atomicAdd(&g_deg[d], ew[e]);
        atomicAdd(&g_counts[d], 1);
    }
}

__global__ void k_dis(int n) {
    int i = blockIdx.x * blockDim.x + threadIdx.x;
    if (i < n) {
        float d = g_deg[i];
        g_dis[i] = (d > 0.0f) ? rsqrtf(d) : 0.0f;
    }
}

__global__ void k_scan1(int n) {
    __shared__ int sh[1024];
    int tid = threadIdx.x;
    int gid = blockIdx.x * 1024 + tid;
    int v = (gid < n) ? g_counts[gid] : 0;
    sh[tid] = v;
    __syncthreads();
    for (int off = 1; off < 1024; off <<= 1) {
        int t = (tid >= off) ? sh[tid - off] : 0;
        __syncthreads();
        sh[tid] += t;
        __syncthreads();
    }
    int incl = sh[tid];
    if (gid < n) g_offsets[gid] = incl - v;       // exclusive
    if (tid == 1023) g_blocksums[blockIdx.x] = incl;
}

__global__ void k_scan2(int nb) {
    __shared__ int sh[64];
    int tid = threadIdx.x;               // 64 threads
    int v = (tid < nb) ? g_blocksums[tid] : 0;
    sh[tid] = v;
    __syncthreads();
    for (int off = 1; off < 64; off <<= 1) {
        int t = (tid >= off) ? sh[tid - off] : 0;
        __syncthreads();
        sh[tid] += t;
        __syncthreads();
    }
    if (tid < nb) g_blocksums[tid] = sh[tid] - v;  // exclusive
}

__global__ void k_scan3(int n) {
    int gid = blockIdx.x * 1024 + threadIdx.x;
    if (gid < n) g_offsets[gid] += g_blocksums[blockIdx.x];
}

__global__ void k_scatter(const int* __restrict__ ei,
                          const float* __restrict__ ew, int E) {
    int e = blockIdx.x * blockDim.x + threadIdx.x;
    if (e < E) {
        int s = ei[e];
        int d = ei[E + e];
        int pos = atomicAdd(&g_offsets[d], 1);
        g_src_sorted[pos]  = s;
        g_norm_sorted[pos] = g_dis[s] * ew[e] * g_dis[d];
    }
}

// ---------------------------------------------------------------------------
// Tensor-core GEMM helpers
// ---------------------------------------------------------------------------
__device__ __forceinline__ uint32_t smem_u32(const void* p) {
    return (uint32_t)__cvta_generic_to_shared(p);
}

__device__ __forceinline__ void ldsm4(uint32_t a[4], uint32_t addr) {
    asm volatile("ldmatrix.sync.aligned.m8n8.x4.shared.b16 {%0,%1,%2,%3}, [%4];"
                 : "=r"(a[0]), "=r"(a[1]), "=r"(a[2]), "=r"(a[3]) : "r"(addr));
}

__device__ __forceinline__ void ldsm4t(uint32_t a[4], uint32_t addr) {
    asm volatile("ldmatrix.sync.aligned.m8n8.x4.trans.shared.b16 {%0,%1,%2,%3}, [%4];"
                 : "=r"(a[0]), "=r"(a[1]), "=r"(a[2]), "=r"(a[3]) : "r"(addr));
}

__device__ __forceinline__ void mma16816(float c[4], const uint32_t a[4],
                                         const uint32_t b[2]) {
    asm volatile(
        "mma.sync.aligned.m16n8k16.row.col.f32.bf16.bf16.f32 "
        "{%0,%1,%2,%3}, {%4,%5,%6,%7}, {%8,%9}, {%0,%1,%2,%3};"
        : "+f"(c[0]), "+f"(c[1]), "+f"(c[2]), "+f"(c[3])
        : "r"(a[0]), "r"(a[1]), "r"(a[2]), "r"(a[3]), "r"(b[0]), "r"(b[1]));
}

__device__ __forceinline__ uint32_t packbf(__nv_bfloat16 a, __nv_bfloat16 b) {
    return ((uint32_t)__bfloat16_as_ushort(b) << 16) | (uint32_t)__bfloat16_as_ushort(a);
}

// Split 8 fp32 values into hi/lo bf16 packed words.
__device__ __forceinline__ void split8(const float v[8], uint32_t h[4], uint32_t l[4]) {
#pragma unroll
    for (int j = 0; j < 4; j++) {
        float v0 = v[2 * j], v1 = v[2 * j + 1];
        __nv_bfloat16 h0 = __float2bfloat16(v0);
        __nv_bfloat16 h1 = __float2bfloat16(v1);
        __nv_bfloat16 l0 = __float2bfloat16(v0 - __bfloat162float(h0));
        __nv_bfloat16 l1 = __float2bfloat16(v1 - __bfloat162float(h1));
        h[j] = packbf(h0, h1);
        l[j] = packbf(l0, l1);
    }
}

// ---------------------------------------------------------------------------
// GEMM: Y[nrows, FOUT] = X[nrows, K] @ W[K, FOUT], fp32 in/out,
// internal 2-term bf16 split on both operands (3 MMAs per logical MMA).
// Block: 256 threads = 8 warps (2 M x 4 N). Tile BM=64, BN=FOUT, BK=64.
// Smem rows are 128B/256B with XOR-swizzled 16B chunks -> conflict-free
// ldmatrix (chunk' = chunk ^ (row & 7) on the low 3 chunk bits).
// ---------------------------------------------------------------------------
template <int K, int FOUT>
__launch_bounds__(256, 2)
__global__ void k_gemm_mma(const float* __restrict__ X, const float* __restrict__ W,
                           float* __restrict__ Y, int nrows) {
    constexpr int BM = 64, BK = 64, BN = FOUT;
    constexpr int WN = BN / 4;            // warp n extent (32 or 16)
    constexpr int NT = WN / 8;            // n mma-tiles per warp (4 or 2)
    constexpr int NG = WN / 16;           // ldmatrix.x4 groups per warp (2 or 1)
    constexpr int ACH = 8;                // 16B chunks per A row (128B = 64 bf16)
    constexpr int BCH = BN / 8;           // 16B chunks per B row
    constexpr int BROWB = BN * 2;         // B smem row bytes

    __shared__ __nv_bfloat16 Ahi[BM * BK];
    __shared__ __nv_bfloat16 Alo[BM * BK];
    __shared__ __nv_bfloat16 Bhi[BK * BN];
    __shared__ __nv_bfloat16 Blo[BK * BN];

    const int tid  = threadIdx.x;
    const int lane = tid & 31;
    const int w    = tid >> 5;
    const int wm   = (w & 1) * 32;        // warp m offset (2 M-warps)
    const int wn   = (w >> 1) * WN;       // warp n offset (4 N-warps)
    const int row0 = blockIdx.x * BM;

    float acc[2][NT][4];
#pragma unroll
    for (int mt = 0; mt < 2; mt++)
#pragma unroll
        for (int nt = 0; nt < NT; nt++)
#pragma unroll
            for (int j = 0; j < 4; j++) acc[mt][nt][j] = 0.0f;

    const uint32_t sAhi = smem_u32(Ahi), sAlo = smem_u32(Alo);
    const uint32_t sBhi = smem_u32(Bhi), sBlo = smem_u32(Blo);

    for (int k0 = 0; k0 < K; k0 += BK) {
        // ---- stage A (64 rows x 64 cols fp32 -> hi/lo bf16, swizzled) ----
#pragma unroll
        for (int i = 0; i < (BM * ACH) / 256; i++) {       // 2 iters
            int idx = tid + i * 256;
            int r = idx >> 3, c = idx & 7;                  // row, chunk
            int gr = row0 + r;
            float v[8];
            if (gr < nrows) {
                const float4* p = (const float4*)(X + (size_t)gr * K + k0 + c * 8);
                float4 f0 = p[0], f1 = p[1];
                v[0] = f0.x; v[1] = f0.y; v[2] = f0.z; v[3] = f0.w;
                v[4] = f1.x; v[5] = f1.y; v[6] = f1.z; v[7] = f1.w;
            } else {
#pragma unroll
                for (int j = 0; j < 8; j++) v[j] = 0.0f;
            }
            uint32_t h[4], l[4];
            split8(v, h, l);
            int dst = r * 128 + ((c ^ (r & 7)) << 4);
            *(uint4*)((char*)Ahi + dst) = make_uint4(h[0], h[1], h[2], h[3]);
            *(uint4*)((char*)Alo + dst) = make_uint4(l[0], l[1], l[2], l[3]);
        }
        // ---- stage B (64 rows x BN cols fp32 -> hi/lo bf16, swizzled) ----
#pragma unroll
        for (int i = 0; i < (BK * BCH) / 256; i++) {       // 4 or 2 iters
            int idx = tid + i * 256;
            int kr = idx / BCH, c = idx % BCH;
            const float4* p = (const float4*)(W + (size_t)(k0 + kr) * FOUT + c * 8);
            float4 f0 = p[0], f1 = p[1];
            float v[8] = {f0.x, f0.y, f0.z, f0.w, f1.x, f1.y, f1.z, f1.w};
            uint32_t h[4], l[4];
            split8(v, h, l);
            int dst = kr * BROWB + ((c ^ (kr & 7)) << 4);
            *(uint4*)((char*)Bhi + dst) = make_uint4(h[0], h[1], h[2], h[3]);
            *(uint4*)((char*)Blo + dst) = make_uint4(l[0], l[1], l[2], l[3]);
        }
        __syncthreads();

        // ---- compute: 4 k16 steps ----
#pragma unroll
        for (int kk = 0; kk < BK / 16; kk++) {
            uint32_t ah[2][4], al[2][4];
#pragma unroll
            for (int mt = 0; mt < 2; mt++) {
                int r = wm + mt * 16 + (lane & 15);
                int c = kk * 2 + (lane >> 4);
                uint32_t off = (uint32_t)(r * 128 + ((c ^ (r & 7)) << 4));
                ldsm4(ah[mt], sAhi + off);
                ldsm4(al[mt], sAlo + off);
            }
            uint32_t bh[NG][4], bl[NG][4];
#pragma unroll
            for (int g = 0; g < NG; g++) {
                int kr = kk * 16 + (lane & 15);
                int c = (wn >> 3) + g * 2 + (lane >> 4);
                uint32_t off = (uint32_t)(kr * BROWB + ((c ^ (kr & 7)) << 4));
                ldsm4t(bh[g], sBhi + off);
                ldsm4t(bl[g], sBlo + off);
            }
#pragma unroll
            for (int mt = 0; mt < 2; mt++)
#pragma unroll
                for (int nt = 0; nt < NT; nt++) {
                    const uint32_t* bhp = &bh[nt >> 1][(nt & 1) * 2];
                    const uint32_t* blp = &bl[nt >> 1][(nt & 1) * 2];
                    mma16816(acc[mt][nt], ah[mt], bhp);   // hi*hi
                    mma16816(acc[mt][nt], al[mt], bhp);   // lo*hi
                    mma16816(acc[mt][nt], ah[mt], blp);   // hi*lo
                }
        }
        __syncthreads();
    }

    // ---- epilogue: scattered float2 stores ----
#pragma unroll
    for (int mt = 0; mt < 2; mt++) {
        int r = row0 + wm + mt * 16 + (lane >> 2);
#pragma unroll
        for (int nt = 0; nt < NT; nt++) {
            int cc = wn + nt * 8 + (lane & 3) * 2;
            if (r < nrows)
                *(float2*)(Y + (size_t)r * FOUT + cc) =
                    make_float2(acc[mt][nt][0], acc[mt][nt][1]);
            if (r + 8 < nrows)
                *(float2*)(Y + (size_t)(r + 8) * FOUT + cc) =
                    make_float2(acc[mt][nt][2], acc[mt][nt][3]);
        }
    }
}

// ---------------------------------------------------------------------------
// Aggregation: one warp per node (unchanged from R1).
// ---------------------------------------------------------------------------
template <int F, bool RELU>
__launch_bounds__(256)
__global__ void k_agg(const float* __restrict__ H, const float* __restrict__ bias,
                      float* __restrict__ out, int n) {
    int warp = (blockIdx.x * blockDim.x + threadIdx.x) >> 5;
    int lane = threadIdx.x & 31;
    if (warp >= n) return;

    constexpr int VEC = F / 32;          // 4 (F=128) or 2 (F=64)
    int s = (warp == 0) ? 0 : g_offsets[warp - 1];
    int e = g_offsets[warp];
    int col = lane * VEC;

    if constexpr (VEC == 4) {
        float4 acc = make_float4(0.f, 0.f, 0.f, 0.f);
        for (int j = s; j < e; j++) {
            int   sn = g_src_sorted[j];
            float nw = g_norm_sorted[j];
            float4 v = *(const float4*)(H + (size_t)sn * F + col);
            acc.x += nw * v.x; acc.y += nw * v.y;
            acc.z += nw * v.z; acc.w += nw * v.w;
        }
        float dv = g_dis[warp];
        float sw = dv * dv;
        float4 v = *(const float4*)(H + (size_t)warp * F + col);
        acc.x += sw * v.x; acc.y += sw * v.y;
        acc.z += sw * v.z; acc.w += sw * v.w;
        float4 b = *(const float4*)(bias + col);
        acc.x += b.x; acc.y += b.y; acc.z += b.z; acc.w += b.w;
        if (RELU) {
            acc.x = fmaxf(acc.x, 0.f); acc.y = fmaxf(acc.y, 0.f);
            acc.z = fmaxf(acc.z, 0.f); acc.w = fmaxf(acc.w, 0.f);
        }
        *(float4*)(out + (size_t)warp * F + col) = acc;
    } else {
        float2 acc = make_float2(0.f, 0.f);
        for (int j = s; j < e; j++) {
            int   sn = g_src_sorted[j];
            float nw = g_norm_sorted[j];
            float2 v = *(const float2*)(H + (size_t)sn * F + col);
            acc.x += nw * v.x; acc.y += nw * v.y;
        }
        float dv = g_dis[warp];
        float sw = dv * dv;
        float2 v = *(const float2*)(H + (size_t)warp * F + col);
        acc.x += sw * v.x; acc.y += sw * v.y;
        float2 b = *(const float2*)(bias + col);
        acc.x += b.x; acc.y += b.y;
        if (RELU) { acc.x = fmaxf(acc.x, 0.f); acc.y = fmaxf(acc.y, 0.f); }
        *(float2*)(out + (size_t)warp * F + col) = acc;
    }
}

// ---------------------------------------------------------------------------
// Launch
// ---------------------------------------------------------------------------
extern "C" void kernel_launch(void* const* d_in, const int* in_sizes, int n_in,
                              void* d_out, int out_size) {
    const float* x  = (const float*)d_in[0];
    const int*   ei = (const int*)  d_in[1];
    const float* ew = (const float*)d_in[2];
    const float* W1 = (const float*)d_in[3];
    const float* b1 = (const float*)d_in[4];
    const float* W2 = (const float*)d_in[5];
    const float* b2 = (const float*)d_in[6];
    const float* W3 = (const float*)d_in[7];
    const float* b3 = (const float*)d_in[8];
    float* out = (float*)d_out;

    const int n = N_NODES;
    const int E = N_EDGES;

    float* bufA;  float* bufB;
    cudaGetSymbolAddress((void**)&bufA, g_bufA);
    cudaGetSymbolAddress((void**)&bufB, g_bufB);

    const int TPB = 256;
    int nbN = (n + TPB - 1) / TPB;
    int nbE = (E + TPB - 1) / TPB;
    int nbScan = (n + 1023) / 1024;     // 49

    // ---- build normalization + CSR ----
    k_init<<<nbN, TPB>>>(n);
    k_deg_count<<<nbE, TPB>>>(ei, ew, E);
    k_dis<<<nbN, TPB>>>(n);
    k_scan1<<<nbScan, 1024>>>(n);
    k_scan2<<<1, 64>>>(nbScan);
    k_scan3<<<nbScan, 1024>>>(n);
    k_scatter<<<nbE, TPB>>>(ei, ew, E);

    int gemmBlocks = (n + 63) / 64;      // BM = 64
    int aggBlocks  = (n * 32 + TPB - 1) / TPB;

    // ---- layer 1: 256 -> 128, relu ----
    k_gemm_mma<256, 128><<<gemmBlocks, 256>>>(x, W1, bufA, n);
    k_agg<128, true><<<aggBlocks, TPB>>>(bufA, b1, bufB, n);

    // ---- layer 2: 128 -> 128, relu ----
    k_gemm_mma<128, 128><<<gemmBlocks, 256>>>(bufB, W2, bufA, n);
    k_agg<128, true><<<aggBlocks, TPB>>>(bufA, b2, bufB, n);

    // ---- layer 3: 128 -> 64, no relu ----
    k_gemm_mma<128, 64><<<gemmBlocks, 256>>>(bufB, W3, bufA, n);
    k_agg<64, false><<<aggBlocks, TPB>>>(bufA, b3, out, n);
}

// round 3
// speedup vs baseline: 1.7082x; 1.1506x over previous
#include <cuda_runtime.h>
#include <cuda_bf16.h>
#include <cuda_fp16.h>
#include <cstdint>

// ---------------------------------------------------------------------------
// GCN: 3 layers. out = Ahat @ (X @ W) + b, relu on layers 1,2.
//
// R3: (1) H written as fp16 by GEMM epilogue; aggregation gathers fp16
//     (halves the L2-bound gather traffic). (2) W pre-converted to bf16
//     hi/lo once. (3) setup trimmed (memsets, packed edge records).
// ---------------------------------------------------------------------------

#define N_NODES 50000
#define N_EDGES 800000

// ----- device scratch (static globals: allocation-free) -----
__device__ float g_deg[N_NODES];
__device__ float g_dis[N_NODES];
__device__ int   g_counts[N_NODES];
__device__ int   g_offsets[N_NODES];     // exclusive starts; mutated by scatter
__device__ int   g_blocksums[64];
__device__ uint2 g_edge[N_EDGES];        // .x = src, .y = float bits of norm
__device__ __half g_bufH[(size_t)N_NODES * 128];   // GEMM output (fp16)
__device__ float  g_bufF[(size_t)N_NODES * 128];   // agg output (fp32)
__device__ __nv_bfloat16 g_Whi[256 * 128 + 128 * 128 + 128 * 64];
__device__ __nv_bfloat16 g_Wlo[256 * 128 + 128 * 128 + 128 * 64];

#define W1_OFF 0
#define W2_OFF (256 * 128)
#define W3_OFF (256 * 128 + 128 * 128)
#define W_TOTAL (256 * 128 + 128 * 128 + 128 * 64)

// ---------------------------------------------------------------------------
// Setup kernels
// ---------------------------------------------------------------------------
__global__ void k_deg_count(const int* __restrict__ ei,
                            const float* __restrict__ ew, int E) {
    int e = blockIdx.x * blockDim.x + threadIdx.x;
    if (e < E) {
        int d = ei[E + e];                 // dst
        atomicAdd(&g_deg[d], ew[e]);
        atomicAdd(&g_counts[d], 1);
    }
}

__global__ void k_dis(int n) {
    int i = blockIdx.x * blockDim.x + threadIdx.x;
    if (i < n) {
        // + 1.0f: self-loop weight folded in (deg+1 >= 1, no zero guard needed)
        g_dis[i] = rsqrtf(g_deg[i] + 1.0f);
    }
}

__global__ void k_scan1(int n) {
    __shared__ int sh[1024];
    int tid = threadIdx.x;
    int gid = blockIdx.x * 1024 + tid;
    int v = (gid < n) ? g_counts[gid] : 0;
    sh[tid] = v;
    __syncthreads();
    for (int off = 1; off < 1024; off <<= 1) {
        int t = (tid >= off) ? sh[tid - off] : 0;
        __syncthreads();
        sh[tid] += t;
        __syncthreads();
    }
    int incl = sh[tid];
    if (gid < n) g_offsets[gid] = incl - v;       // exclusive
    if (tid == 1023) g_blocksums[blockIdx.x] = incl;
}

__global__ void k_scan2(int nb) {
    __shared__ int sh[64];
    int tid = threadIdx.x;               // 64 threads
    int v = (tid < nb) ? g_blocksums[tid] : 0;
    sh[tid] = v;
    __syncthreads();
    for (int off = 1; off < 64; off <<= 1) {
        int t = (tid >= off) ? sh[tid - off] : 0;
        __syncthreads();
        sh[tid] += t;
        __syncthreads();
    }
    if (tid < nb) g_blocksums[tid] = sh[tid] - v;  // exclusive
}

__global__ void k_scan3(int n) {
    int gid = blockIdx.x * 1024 + threadIdx.x;
    if (gid < n) g_offsets[gid] += g_blocksums[blockIdx.x];
}

__global__ void k_scatter(const int* __restrict__ ei,
                          const float* __restrict__ ew, int E) {
    int e = blockIdx.x * blockDim.x + threadIdx.x;
    if (e < E) {
        int s = ei[e];
        int d = ei[E + e];
        int pos = atomicAdd(&g_offsets[d], 1);
        float nw = g_dis[s] * ew[e] * g_dis[d];
        g_edge[pos] = make_uint2((uint32_t)s, __float_as_uint(nw));
    }
}

// Convert all three W matrices fp32 -> bf16 hi/lo (once per call).
__global__ void k_convW(const float* __restrict__ W1, const float* __restrict__ W2,
                        const float* __restrict__ W3) {
    int i = blockIdx.x * blockDim.x + threadIdx.x;
    if (i >= W_TOTAL) return;
    float v;
    if (i < W2_OFF)       v = W1[i];
    else if (i < W3_OFF)  v = W2[i - W2_OFF];
    else                  v = W3[i - W3_OFF];
    __nv_bfloat16 h = __float2bfloat16(v);
    __nv_bfloat16 l = __float2bfloat16(v - __bfloat162float(h));
    g_Whi[i] = h;
    g_Wlo[i] = l;
}

// ---------------------------------------------------------------------------
// Tensor-core GEMM helpers
// ---------------------------------------------------------------------------
__device__ __forceinline__ uint32_t smem_u32(const void* p) {
    return (uint32_t)__cvta_generic_to_shared(p);
}

__device__ __forceinline__ void ldsm4(uint32_t a[4], uint32_t addr) {
    asm volatile("ldmatrix.sync.aligned.m8n8.x4.shared.b16 {%0,%1,%2,%3}, [%4];"
                 : "=r"(a[0]), "=r"(a[1]), "=r"(a[2]), "=r"(a[3]) : "r"(addr));
}

__device__ __forceinline__ void ldsm4t(uint32_t a[4], uint32_t addr) {
    asm volatile("ldmatrix.sync.aligned.m8n8.x4.trans.shared.b16 {%0,%1,%2,%3}, [%4];"
                 : "=r"(a[0]), "=r"(a[1]), "=r"(a[2]), "=r"(a[3]) : "r"(addr));
}

__device__ __forceinline__ void mma16816(float c[4], const uint32_t a[4],
                                         const uint32_t b[2]) {
    asm volatile(
        "mma.sync.aligned.m16n8k16.row.col.f32.bf16.bf16.f32 "
        "{%0,%1,%2,%3}, {%4,%5,%6,%7}, {%8,%9}, {%0,%1,%2,%3};"
        : "+f"(c[0]), "+f"(c[1]), "+f"(c[2]), "+f"(c[3])
        : "r"(a[0]), "r"(a[1]), "r"(a[2]), "r"(a[3]), "r"(b[0]), "r"(b[1]));
}

__device__ __forceinline__ uint32_t packbf(__nv_bfloat16 a, __nv_bfloat16 b) {
    return ((uint32_t)__bfloat16_as_ushort(b) << 16) | (uint32_t)__bfloat16_as_ushort(a);
}

__device__ __forceinline__ void split8(const float v[8], uint32_t h[4], uint32_t l[4]) {
#pragma unroll
    for (int j = 0; j < 4; j++) {
        float v0 = v[2 * j], v1 = v[2 * j + 1];
        __nv_bfloat16 h0 = __float2bfloat16(v0);
        __nv_bfloat16 h1 = __float2bfloat16(v1);
        __nv_bfloat16 l0 = __float2bfloat16(v0 - __bfloat162float(h0));
        __nv_bfloat16 l1 = __float2bfloat16(v1 - __bfloat162float(h1));
        h[j] = packbf(h0, h1);
        l[j] = packbf(l0, l1);
    }
}

// ---------------------------------------------------------------------------
// GEMM: Yh[nrows, FOUT] (fp16) = X[nrows, K] (fp32) @ W[K, FOUT] (bf16 hi/lo).
// 2-term bf16 split: hi*hi + lo*hi + hi*lo (error ~2^-16).
// Block: 256 threads = 8 warps (2 M x 4 N). Tile BM=64, BN=FOUT, BK=64.
// XOR-swizzled 16B chunks -> conflict-free ldmatrix.
// ---------------------------------------------------------------------------
template <int K, int FOUT>
__launch_bounds__(256, 2)
__global__ void k_gemm_mma(const float* __restrict__ X,
                           const __nv_bfloat16* __restrict__ Whi,
                           const __nv_bfloat16* __restrict__ Wlo,
                           __half* __restrict__ Yh, int nrows) {
    constexpr int BM = 64, BK = 64, BN = FOUT;
    constexpr int WN = BN / 4;            // warp n extent (32 or 16)
    constexpr int NT = WN / 8;            // n mma-tiles per warp (4 or 2)
    constexpr int NG = WN / 16;           // ldmatrix.x4 groups per warp (2 or 1)
    constexpr int ACH = 8;                // 16B chunks per A row
    constexpr int BCH = BN / 8;           // 16B chunks per B row
    constexpr int BROWB = BN * 2;         // B smem row bytes

    __shared__ __nv_bfloat16 Ahi[BM * BK];
    __shared__ __nv_bfloat16 Alo[BM * BK];
    __shared__ __nv_bfloat16 Bhi[BK * BN];
    __shared__ __nv_bfloat16 Blo[BK * BN];

    const int tid  = threadIdx.x;
    const int lane = tid & 31;
    const int w    = tid >> 5;
    const int wm   = (w & 1) * 32;
    const int wn   = (w >> 1) * WN;
    const int row0 = blockIdx.x * BM;

    float acc[2][NT][4];
#pragma unroll
    for (int mt = 0; mt < 2; mt++)
#pragma unroll
        for (int nt = 0; nt < NT; nt++)
#pragma unroll
            for (int j = 0; j < 4; j++) acc[mt][nt][j] = 0.0f;

    const uint32_t sAhi = smem_u32(Ahi), sAlo = smem_u32(Alo);
    const uint32_t sBhi = smem_u32(Bhi), sBlo = smem_u32(Blo);

    for (int k0 = 0; k0 < K; k0 += BK) {
        // ---- stage A (fp32 -> hi/lo bf16 split, swizzled) ----
#pragma unroll
        for (int i = 0; i < (BM * ACH) / 256; i++) {       // 2 iters
            int idx = tid + i * 256;
            int r = idx >> 3, c = idx & 7;
            int gr = row0 + r;
            float v[8];
            if (gr < nrows) {
                const float4* p = (const float4*)(X + (size_t)gr * K + k0 + c * 8);
                float4 f0 = p[0], f1 = p[1];
                v[0] = f0.x; v[1] = f0.y; v[2] = f0.z; v[3] = f0.w;
                v[4] = f1.x; v[5] = f1.y; v[6] = f1.z; v[7] = f1.w;
            } else {
#pragma unroll
                for (int j = 0; j < 8; j++) v[j] = 0.0f;
            }
            uint32_t h[4], l[4];
            split8(v, h, l);
            int dst = r * 128 + ((c ^ (r & 7)) << 4);
            *(uint4*)((char*)Ahi + dst) = make_uint4(h[0], h[1], h[2], h[3]);
            *(uint4*)((char*)Alo + dst) = make_uint4(l[0], l[1], l[2], l[3]);
        }
        // ---- stage B: direct bf16 uint4 copies from pre-converted W ----
        {
            constexpr int CPB = BK * BCH;                  // uint4 chunks per buffer
#pragma unroll
            for (int i = 0; i < (2 * CPB) / 256; i++) {    // 8 (BN=128) / 4 (BN=64)
                int idx = tid + i * 256;
                int buf = idx / CPB;
                int rem = idx - buf * CPB;
                int kr = rem / BCH, c = rem % BCH;
                const uint4* src = (const uint4*)(buf ? Wlo : Whi);
                uint4 v = src[(size_t)(k0 + kr) * BCH + c];
                int dst = kr * BROWB + ((c ^ (kr & 7)) << 4);
                *(uint4*)((char*)(buf ? Blo : Bhi) + dst) = v;
            }
        }
        __syncthreads();

        // ---- compute: 4 k16 steps ----
#pragma unroll
        for (int kk = 0; kk < BK / 16; kk++) {
            uint32_t ah[2][4], al[2][4];
#pragma unroll
            for (int mt = 0; mt < 2; mt++) {
                int r = wm + mt * 16 + (lane & 15);
                int c = kk * 2 + (lane >> 4);
                uint32_t off = (uint32_t)(r * 128 + ((c ^ (r & 7)) << 4));
                ldsm4(ah[mt], sAhi + off);
                ldsm4(al[mt], sAlo + off);
            }
            uint32_t bh[NG][4], bl[NG][4];
#pragma unroll
            for (int g = 0; g < NG; g++) {
                int kr = kk * 16 + (lane & 15);
                int c = (wn >> 3) + g * 2 + (lane >> 4);
                uint32_t off = (uint32_t)(kr * BROWB + ((c ^ (kr & 7)) << 4));
                ldsm4t(bh[g], sBhi + off);
                ldsm4t(bl[g], sBlo + off);
            }
#pragma unroll
            for (int mt = 0; mt < 2; mt++)
#pragma unroll
                for (int nt = 0; nt < NT; nt++) {
                    const uint32_t* bhp = &bh[nt >> 1][(nt & 1) * 2];
                    const uint32_t* blp = &bl[nt >> 1][(nt & 1) * 2];
                    mma16816(acc[mt][nt], ah[mt], bhp);   // hi*hi
                    mma16816(acc[mt][nt], al[mt], bhp);   // lo*hi
                    mma16816(acc[mt][nt], ah[mt], blp);   // hi*lo
                }
        }
        __syncthreads();
    }

    // ---- epilogue: fp16 stores ----
#pragma unroll
    for (int mt = 0; mt < 2; mt++) {
        int r = row0 + wm + mt * 16 + (lane >> 2);
#pragma unroll
        for (int nt = 0; nt < NT; nt++) {
            int cc = wn + nt * 8 + (lane & 3) * 2;
            if (r < nrows)
                *(__half2*)(Yh + (size_t)r * FOUT + cc) =
                    __floats2half2_rn(acc[mt][nt][0], acc[mt][nt][1]);
            if (r + 8 < nrows)
                *(__half2*)(Yh + (size_t)(r + 8) * FOUT + cc) =
                    __floats2half2_rn(acc[mt][nt][2], acc[mt][nt][3]);
        }
    }
}

// ---------------------------------------------------------------------------
// Aggregation: one warp per node, fp16 gathers, fp32 accumulate.
// out[i] = sum_e norm_e * H[src_e] + dis[i]^2 * H[i] + b   (optional relu)
// ---------------------------------------------------------------------------
template <int F, bool RELU>
__launch_bounds__(256)
__global__ void k_agg(const __half* __restrict__ H, const float* __restrict__ bias,
                      float* __restrict__ out, int n) {
    int warp = (blockIdx.x * blockDim.x + threadIdx.x) >> 5;
    int lane = threadIdx.x & 31;
    if (warp >= n) return;

    constexpr int VEC = F / 32;          // 4 (F=128) or 2 (F=64)
    int s = (warp == 0) ? 0 : g_offsets[warp - 1];
    int e = g_offsets[warp];
    int col = lane * VEC;

    if constexpr (VEC == 4) {
        float4 acc = make_float4(0.f, 0.f, 0.f, 0.f);
        for (int j = s; j < e; j++) {
            uint2  ed = g_edge[j];
            float  nw = __uint_as_float(ed.y);
            uint2  raw = *(const uint2*)(H + (size_t)ed.x * F + col);
            float2 f0 = __half22float2(*(__half2*)&raw.x);
            float2 f1 = __half22float2(*(__half2*)&raw.y);
            acc.x += nw * f0.x; acc.y += nw * f0.y;
            acc.z += nw * f1.x; acc.w += nw * f1.y;
        }
        float dv = g_dis[warp];
        float sw = dv * dv;
        uint2 raw = *(const uint2*)(H + (size_t)warp * F + col);
        float2 f0 = __half22float2(*(__half2*)&raw.x);
        float2 f1 = __half22float2(*(__half2*)&raw.y);
        acc.x += sw * f0.x; acc.y += sw * f0.y;
        acc.z += sw * f1.x; acc.w += sw * f1.y;
        float4 b = *(const float4*)(bias + col);
        acc.x += b.x; acc.y += b.y; acc.z += b.z; acc.w += b.w;
        if (RELU) {
            acc.x = fmaxf(acc.x, 0.f); acc.y = fmaxf(acc.y, 0.f);
            acc.z = fmaxf(acc.z, 0.f); acc.w = fmaxf(acc.w, 0.f);
        }
        *(float4*)(out + (size_t)warp * F + col) = acc;
    } else {
        float2 acc = make_float2(0.f, 0.f);
        for (int j = s; j < e; j++) {
            uint2  ed = g_edge[j];
            float  nw = __uint_as_float(ed.y);
            uint32_t raw = *(const uint32_t*)(H + (size_t)ed.x * F + col);
            float2 f0 = __half22float2(*(__half2*)&raw);
            acc.x += nw * f0.x; acc.y += nw * f0.y;
        }
        float dv = g_dis[warp];
        float sw = dv * dv;
        uint32_t raw = *(const uint32_t*)(H + (size_t)warp * F + col);
        float2 f0 = __half22float2(*(__half2*)&raw);
        acc.x += sw * f0.x; acc.y += sw * f0.y;
        float2 b = *(const float2*)(bias + col);
        acc.x += b.x; acc.y += b.y;
        if (RELU) { acc.x = fmaxf(acc.x, 0.f); acc.y = fmaxf(acc.y, 0.f); }
        *(float2*)(out + (size_t)warp * F + col) = acc;
    }
}

// ---------------------------------------------------------------------------
// Launch
// ---------------------------------------------------------------------------
extern "C" void kernel_launch(void* const* d_in, const int* in_sizes, int n_in,
                              void* d_out, int out_size) {
    const float* x  = (const float*)d_in[0];
    const int*   ei = (const int*)  d_in[1];
    const float* ew = (const float*)d_in[2];
    const float* W1 = (const float*)d_in[3];
    const float* b1 = (const float*)d_in[4];
    const float* W2 = (const float*)d_in[5];
    const float* b2 = (const float*)d_in[6];
    const float* W3 = (const float*)d_in[7];
    const float* b3 = (const float*)d_in[8];
    float* out = (float*)d_out;

    const int n = N_NODES;
    const int E = N_EDGES;

    __half* bufH;  float* bufF;
    __nv_bfloat16 *Whi, *Wlo;
    void* p;
    cudaGetSymbolAddress(&p, g_bufH); bufH = (__half*)p;
    cudaGetSymbolAddress(&p, g_bufF); bufF = (float*)p;
    cudaGetSymbolAddress(&p, g_Whi);  Whi  = (__nv_bfloat16*)p;
    cudaGetSymbolAddress(&p, g_Wlo);  Wlo  = (__nv_bfloat16*)p;
    void* degP; cudaGetSymbolAddress(&degP, g_deg);
    void* cntP; cudaGetSymbolAddress(&cntP, g_counts);

    const int TPB = 256;
    int nbN = (n + TPB - 1) / TPB;
    int nbE = (E + TPB - 1) / TPB;
    int nbScan = (n + 1023) / 1024;     // 49

    // ---- W pre-conversion (independent) ----
    k_convW<<<(W_TOTAL + TPB - 1) / TPB, TPB>>>(W1, W2, W3);

    // ---- build normalization + CSR ----
    cudaMemsetAsync(degP, 0, (size_t)n * sizeof(float));
    cudaMemsetAsync(cntP, 0, (size_t)n * sizeof(int));
    k_deg_count<<<nbE, TPB>>>(ei, ew, E);
    k_dis<<<nbN, TPB>>>(n);
    k_scan1<<<nbScan, 1024>>>(n);
    k_scan2<<<1, 64>>>(nbScan);
    k_scan3<<<nbScan, 1024>>>(n);
    k_scatter<<<nbE, TPB>>>(ei, ew, E);

    int gemmBlocks = (n + 63) / 64;      // BM = 64
    int aggBlocks  = (n * 32 + TPB - 1) / TPB;

    // ---- layer 1: 256 -> 128, relu ----
    k_gemm_mma<256, 128><<<gemmBlocks, 256>>>(x, Whi + W1_OFF, Wlo + W1_OFF, bufH, n);
    k_agg<128, true><<<aggBlocks, TPB>>>(bufH, b1, bufF, n);

    // ---- layer 2: 128 -> 128, relu ----
    k_gemm_mma<128, 128><<<gemmBlocks, 256>>>(bufF, Whi + W2_OFF, Wlo + W2_OFF, bufH, n);
    k_agg<128, true><<<aggBlocks, TPB>>>(bufH, b2, bufF, n);

    // ---- layer 3: 128 -> 64, no relu ----
    k_gemm_mma<128, 64><<<gemmBlocks, 256>>>(bufF, Whi + W3_OFF, Wlo + W3_OFF, bufH, n);
    k_agg<64, false><<<aggBlocks, TPB>>>(bufH, b3, out, n);
}